// round 5
// baseline (speedup 1.0000x reference)
#include <cuda_runtime.h>
#include <cuda_bf16.h>
#include <math.h>

#define TSEQ 8192
#define HID 512
#define DIN0 1728
#define GDIM 2048   // 4*HID
#define NTAGS 27
#define START_TAG 25
#define STOP_TAG 26

// ---------------- static device scratch (no allocations allowed) -------------
__device__ float d_x[TSEQ * DIN0];          // conv features
__device__ float d_g0f[TSEQ * GDIM];        // layer0 fwd input-gates
__device__ float d_g0r[TSEQ * GDIM];        // layer0 bwd input-gates
__device__ float d_h0[TSEQ * 1024];         // layer0 output (fwd|bwd), plain
__device__ float d_g1f[TSEQ * GDIM];
__device__ float d_g1r[TSEQ * GDIM];
__device__ float d_h1[TSEQ * 1024];
__device__ float d_feats[TSEQ * NTAGS];
// tagged h pairs: [dir][t][512] of (tag<<32 | float_bits); one buffer per layer
__device__ unsigned long long d_hp0[2 * TSEQ * 512];
__device__ unsigned long long d_hp1[2 * TSEQ * 512];

// ---------------- pair-buffer reset + output fill ----------------------------
__global__ void fill_pairs_kernel() {
    int i = blockIdx.x * blockDim.x + threadIdx.x;
    int n4 = (2 * TSEQ * 512) / 2;   // uint4 = 2 ull
    uint4 z = make_uint4(0u, 0u, 0u, 0u);
    if (i < n4) {
        ((uint4*)d_hp0)[i] = z;
        ((uint4*)d_hp1)[i] = z;
    }
}

__global__ void fill_out_kernel(float* out, int n) {
    int i = blockIdx.x * blockDim.x + threadIdx.x;
    if (i < n) out[i] = 0.0f;
}

// ---------------- conv front-end ---------------------------------------------
__global__ void conv_kernel(const float* __restrict__ features,
                            const float* __restrict__ w1, const float* __restrict__ b1,
                            const float* __restrict__ w3, const float* __restrict__ b3,
                            const float* __restrict__ w5, const float* __restrict__ b5) {
    __shared__ float f[448];
    int t = blockIdx.x, tid = threadIdx.x;
    for (int i = tid; i < 448; i += blockDim.x) f[i] = features[t * 448 + i];
    __syncthreads();
    for (int idx = tid; idx < DIN0; idx += blockDim.x) {
        float s;
        if (idx < 192) {
            int c = idx / 12, w = idx % 12;
            s = b1[c];
            #pragma unroll
            for (int kh = 0; kh < 7; kh++)
                #pragma unroll
                for (int kw = 0; kw < 4; kw++)
                    s = fmaf(f[kh * 64 + w * 4 + kw], w1[c * 28 + kh * 4 + kw], s);
        } else if (idx < 960) {
            int j = idx - 192;
            int c = j / 48, h = (j % 48) / 12, w = j % 12;
            s = b3[c];
            #pragma unroll
            for (int kh = 0; kh < 4; kh++)
                #pragma unroll
                for (int kw = 0; kw < 12; kw++)
                    s = fmaf(f[(h + kh) * 64 + w * 4 + kw], w3[c * 48 + kh * 12 + kw], s);
        } else {
            int j = idx - 960;
            int c = j / 48, h = (j % 48) / 12, w = j % 12;
            s = b5[c];
            #pragma unroll
            for (int kh = 0; kh < 4; kh++)
                #pragma unroll
                for (int kw = 0; kw < 20; kw++)
                    s = fmaf(f[(h + kh) * 64 + w * 4 + kw], w5[c * 80 + kh * 20 + kw], s);
        }
        d_x[t * DIN0 + idx] = s;
    }
}

// ---------------- GEMM: C = A[M,K] * B[N,K]^T + (bi + bh), N = 2048 ----------
// Double-buffered SMEM, ONE __syncthreads per k-tile.
__global__ void __launch_bounds__(256)
gemm_bias_kernel(const float* __restrict__ A, int K,
                 const float* __restrict__ Bf, const float* __restrict__ Br,
                 const float* __restrict__ bif, const float* __restrict__ bhf,
                 const float* __restrict__ bir, const float* __restrict__ bhr,
                 float* __restrict__ Cf, float* __restrict__ Cr) {
    const float* B  = blockIdx.z ? Br  : Bf;
    const float* bi = blockIdx.z ? bir : bif;
    const float* bh = blockIdx.z ? bhr : bhf;
    float*       C  = blockIdx.z ? Cr  : Cf;

    __shared__ float As[2][16][132];
    __shared__ float Bs[2][16][132];

    int tid = threadIdx.x;
    int m0 = blockIdx.y * 128, n0 = blockIdx.x * 128;
    int tm = (tid >> 4) * 8;
    int tn = (tid & 15) * 8;

    float acc[8][8];
    #pragma unroll
    for (int i = 0; i < 8; i++)
        #pragma unroll
        for (int j = 0; j < 8; j++) acc[i][j] = 0.0f;

    int lr = tid >> 2;
    int lc = (tid & 3) * 4;
    const float* Ap = A + (size_t)(m0 + lr) * K + lc;
    const float* Bp = B + (size_t)(n0 + lr) * K + lc;

    int nk = K / 16;
    float4 ra0, ra1, rb0, rb1;   // staged tile in registers

    // prologue: tile0 -> smem[0]; tile1 -> regs
    ra0 = *(const float4*)(Ap);
    ra1 = *(const float4*)(Ap + (size_t)64 * K);
    rb0 = *(const float4*)(Bp);
    rb1 = *(const float4*)(Bp + (size_t)64 * K);
    As[0][lc + 0][lr] = ra0.x; As[0][lc + 1][lr] = ra0.y; As[0][lc + 2][lr] = ra0.z; As[0][lc + 3][lr] = ra0.w;
    As[0][lc + 0][lr + 64] = ra1.x; As[0][lc + 1][lr + 64] = ra1.y; As[0][lc + 2][lr + 64] = ra1.z; As[0][lc + 3][lr + 64] = ra1.w;
    Bs[0][lc + 0][lr] = rb0.x; Bs[0][lc + 1][lr] = rb0.y; Bs[0][lc + 2][lr] = rb0.z; Bs[0][lc + 3][lr] = rb0.w;
    Bs[0][lc + 0][lr + 64] = rb1.x; Bs[0][lc + 1][lr + 64] = rb1.y; Bs[0][lc + 2][lr + 64] = rb1.z; Bs[0][lc + 3][lr + 64] = rb1.w;
    if (nk > 1) {
        ra0 = *(const float4*)(Ap + 16);
        ra1 = *(const float4*)(Ap + (size_t)64 * K + 16);
        rb0 = *(const float4*)(Bp + 16);
        rb1 = *(const float4*)(Bp + (size_t)64 * K + 16);
    }
    __syncthreads();

    int cur = 0;
    for (int i = 0; i < nk; ++i) {
        // store staged tile i+1 into the other buffer (safe: its last compute
        // finished before the previous __syncthreads)
        if (i + 1 < nk) {
            int nb = cur ^ 1;
            As[nb][lc + 0][lr] = ra0.x; As[nb][lc + 1][lr] = ra0.y; As[nb][lc + 2][lr] = ra0.z; As[nb][lc + 3][lr] = ra0.w;
            As[nb][lc + 0][lr + 64] = ra1.x; As[nb][lc + 1][lr + 64] = ra1.y; As[nb][lc + 2][lr + 64] = ra1.z; As[nb][lc + 3][lr + 64] = ra1.w;
            Bs[nb][lc + 0][lr] = rb0.x; Bs[nb][lc + 1][lr] = rb0.y; Bs[nb][lc + 2][lr] = rb0.z; Bs[nb][lc + 3][lr] = rb0.w;
            Bs[nb][lc + 0][lr + 64] = rb1.x; Bs[nb][lc + 1][lr + 64] = rb1.y; Bs[nb][lc + 2][lr + 64] = rb1.z; Bs[nb][lc + 3][lr + 64] = rb1.w;
        }
        // prefetch tile i+2 into regs (two iterations of latency cover)
        if (i + 2 < nk) {
            int k0 = (i + 2) * 16;
            ra0 = *(const float4*)(Ap + k0);
            ra1 = *(const float4*)(Ap + (size_t)64 * K + k0);
            rb0 = *(const float4*)(Bp + k0);
            rb1 = *(const float4*)(Bp + (size_t)64 * K + k0);
        }
        // compute on current buffer
        #pragma unroll
        for (int kk = 0; kk < 16; kk++) {
            float4 av0 = *(const float4*)(&As[cur][kk][tm]);
            float4 av1 = *(const float4*)(&As[cur][kk][tm + 4]);
            float4 bv0 = *(const float4*)(&Bs[cur][kk][tn]);
            float4 bv1 = *(const float4*)(&Bs[cur][kk][tn + 4]);
            float ar[8] = {av0.x, av0.y, av0.z, av0.w, av1.x, av1.y, av1.z, av1.w};
            float br[8] = {bv0.x, bv0.y, bv0.z, bv0.w, bv1.x, bv1.y, bv1.z, bv1.w};
            #pragma unroll
            for (int ii = 0; ii < 8; ii++)
                #pragma unroll
                for (int jj = 0; jj < 8; jj++)
                    acc[ii][jj] = fmaf(ar[ii], br[jj], acc[ii][jj]);
        }
        __syncthreads();
        cur ^= 1;
    }

    #pragma unroll
    for (int j = 0; j < 8; j++) {
        float bb = bi[n0 + tn + j] + bh[n0 + tn + j];
        #pragma unroll
        for (int i = 0; i < 8; i++)
            C[(size_t)(m0 + tm + i) * GDIM + n0 + tn + j] = acc[i][j] + bb;
    }
}

// ---------------- fast activations (saturating, __expf-based) ----------------
__device__ __forceinline__ float sigmoid_fast(float x) {
    return __fdividef(1.0f, 1.0f + __expf(-x));
}
__device__ __forceinline__ float tanh_fast(float x) {
    return 1.0f - __fdividef(2.0f, __expf(2.0f * x) + 1.0f);
}

// ---------------- persistent bidirectional LSTM recurrence -------------------
// Sync: tag embedded in the h word (st/ld.relaxed.gpu.u64, single-copy atomic).
// Activation applied per-lane BEFORE the gate shuffle (tanh via sigmoid
// identity) so the post-shuffle serial chain is just fma + tanh(cst) + mul.
__global__ void __launch_bounds__(256, 1)
lstm_rec_kernel(const float* __restrict__ gxf, const float* __restrict__ gxr,
                const float* __restrict__ whhf, const float* __restrict__ whhr,
                float* __restrict__ hout, unsigned long long* hpairBase) {
    int b = blockIdx.x;
    int dir = b >> 6;                 // 0 fwd, 1 bwd
    int blk = b & 63;
    int cell0 = blk * 8;
    const float* gx  = dir ? gxr  : gxf;
    const float* whh = dir ? whhr : whhf;
    unsigned long long* hp = hpairBase + (size_t)dir * TSEQ * 512;

    int tid = threadIdx.x;
    int row = tid & 31;               // local gate row 0..31
    int seg = tid >> 5;               // 0..7 (64-wide h segment)
    int q = row >> 3, c = row & 7;
    int gr = q * HID + cell0 + c;     // global gate row in whh

    float4 w4[16];
    {
        const float4* wp = (const float4*)(whh + (size_t)gr * HID + seg * 64);
        #pragma unroll
        for (int i = 0; i < 16; i++) w4[i] = wp[i];
    }

    __shared__ float h_sm[512];
    __shared__ float partial[256];

    float cst = 0.0f;                 // cell state (valid on tid<8)
    bool tanh_lane = (row >= 16) && (row < 24);

    // prefetch gx for step 0
    float gxv = 0.0f;
    if (tid < 32) {
        int t0 = dir ? (TSEQ - 1) : 0;
        gxv = __ldcg(gx + (size_t)t0 * GDIM + gr);
    }

    for (int s = 0; s < TSEQ; ++s) {
        int t = dir ? (TSEQ - 1 - s) : s;

        // prefetch gx for step s+1 (a full step of latency cover)
        float gx_next = 0.0f;
        if (tid < 32 && s + 1 < TSEQ) {
            int tn = dir ? (TSEQ - 2 - s) : (s + 1);
            gx_next = __ldcg(gx + (size_t)tn * GDIM + gr);
        }

        if (s > 0) {
            int tprev = dir ? (t + 1) : (t - 1);
            const unsigned long long* p0 = hp + (size_t)tprev * 512 + tid;
            const unsigned long long* p1 = p0 + 256;
            unsigned int want = (unsigned int)s;
            unsigned long long v0, v1;
            do {
                asm volatile("ld.relaxed.gpu.global.u64 %0, [%1];"
                             : "=l"(v0) : "l"(p0) : "memory");
                asm volatile("ld.relaxed.gpu.global.u64 %0, [%1];"
                             : "=l"(v1) : "l"(p1) : "memory");
            } while ((unsigned int)(v0 >> 32) != want ||
                     (unsigned int)(v1 >> 32) != want);
            h_sm[tid]       = __uint_as_float((unsigned int)v0);
            h_sm[tid + 256] = __uint_as_float((unsigned int)v1);
        } else {
            h_sm[tid] = 0.0f;
            h_sm[tid + 256] = 0.0f;
        }
        __syncthreads();

        // 64-wide partial dot, 4 independent accumulator chains (depth 16)
        float a0 = 0.f, a1 = 0.f, a2 = 0.f, a3 = 0.f;
        const float4* hv4 = (const float4*)(h_sm + seg * 64);
        #pragma unroll
        for (int i = 0; i < 16; i++) {
            float4 h = hv4[i];
            a0 = fmaf(w4[i].x, h.x, a0);
            a1 = fmaf(w4[i].y, h.y, a1);
            a2 = fmaf(w4[i].z, h.z, a2);
            a3 = fmaf(w4[i].w, h.w, a3);
        }
        partial[tid] = (a0 + a1) + (a2 + a3);
        __syncthreads();

        if (tid < 32) {
            float g = gxv;
            float s0 = partial[row]       + partial[32 + row];
            float s1 = partial[64 + row]  + partial[96 + row];
            float s2 = partial[128 + row] + partial[160 + row];
            float s3 = partial[192 + row] + partial[224 + row];
            g += (s0 + s1) + (s2 + s3);
            // per-lane activation (parallel): sigmoid, or tanh = 2*sig(2x)-1
            float xx = tanh_lane ? 2.0f * g : g;
            float sg = __fdividef(1.0f, 1.0f + __expf(-xx));
            float act = tanh_lane ? 2.0f * sg - 1.0f : sg;
            float fi = __shfl_sync(0xffffffffu, act, c);
            float ff = __shfl_sync(0xffffffffu, act, 8 + c);
            float gt = __shfl_sync(0xffffffffu, act, 16 + c);
            float fo = __shfl_sync(0xffffffffu, act, 24 + c);
            if (tid < 8) {
                cst = ff * cst + fi * gt;
                float hv = fo * tanh_fast(cst);
                // plain copy for downstream kernels (kernel-order visibility)
                __stcg(hout + (size_t)t * 1024 + dir * HID + cell0 + c, hv);
                // tagged word: the sync carrier
                unsigned long long pv =
                    ((unsigned long long)(unsigned int)(s + 1) << 32) |
                    (unsigned long long)__float_as_uint(hv);
                unsigned long long* dst = hp + (size_t)t * 512 + cell0 + c;
                asm volatile("st.relaxed.gpu.global.u64 [%0], %1;"
                             :: "l"(dst), "l"(pv) : "memory");
            }
        }
        gxv = gx_next;
    }
}

// ---------------- hidden -> tag scores ---------------------------------------
__global__ void h2t_kernel(const float* __restrict__ h, const float* __restrict__ W,
                           const float* __restrict__ bt) {
    int t = blockIdx.x;
    int lane = threadIdx.x & 31, wrp = threadIdx.x >> 5;   // 4 warps
    for (int tag = wrp; tag < NTAGS; tag += 4) {
        float s = 0.0f;
        const float* hr = h + (size_t)t * 1024;
        const float* wr = W + (size_t)tag * 1024;
        for (int k = lane; k < 1024; k += 32) s = fmaf(hr[k], wr[k], s);
        #pragma unroll
        for (int o = 16; o; o >>= 1) s += __shfl_xor_sync(0xffffffffu, s, o);
        if (lane == 0) d_feats[t * NTAGS + tag] = s + bt[tag];
    }
}

// ---------------- Viterbi: 1 warp, SMEM fv broadcast, 4 contiguous chains ----
__global__ void viterbi_kernel(const float* __restrict__ trans,
                               float* __restrict__ out, int out_size) {
    extern __shared__ unsigned char bp[];   // [TSEQ][27] bytes (dynamic)
    __shared__ float fvs[28];
    int lane = threadIdx.x;

    float tr[28];
    #pragma unroll
    for (int p = 0; p < 28; p++)
        tr[p] = (lane < NTAGS && p < NTAGS) ? trans[lane * NTAGS + p] : -1e30f;

    float fv = (lane == START_TAG) ? 0.0f : -10000.0f;
    if (lane >= NTAGS) fv = -1e30f;
    if (lane == 0) fvs[27] = -1e30f;
    __syncwarp();

    for (int t = 0; t < TSEQ; t++) {
        float ft = (lane < NTAGS) ? __ldg(&d_feats[t * NTAGS + lane]) : 0.0f;
        if (lane < NTAGS) fvs[lane] = fv;
        __syncwarp();

        float m0 = -3.4e38f, m1 = -3.4e38f, m2 = -3.4e38f, m3 = -3.4e38f;
        int a0 = 0, a1 = 7, a2 = 14, a3 = 21;
        #pragma unroll
        for (int j = 0; j < 7; j++) {
            float s = fvs[j] + tr[j];
            if (s > m0) { m0 = s; a0 = j; }
        }
        #pragma unroll
        for (int j = 7; j < 14; j++) {
            float s = fvs[j] + tr[j];
            if (s > m1) { m1 = s; a1 = j; }
        }
        #pragma unroll
        for (int j = 14; j < 21; j++) {
            float s = fvs[j] + tr[j];
            if (s > m2) { m2 = s; a2 = j; }
        }
        #pragma unroll
        for (int j = 21; j < 28; j++) {
            float s = fvs[j] + tr[j];
            if (s > m3) { m3 = s; a3 = j; }
        }
        float m = m0; int a = a0;
        if (m1 > m) { m = m1; a = a1; }
        if (m2 > m) { m = m2; a = a2; }
        if (m3 > m) { m = m3; a = a3; }

        if (lane < NTAGS) bp[t * NTAGS + lane] = (unsigned char)a;
        fv = m + ft;
        __syncwarp();
    }

    float term = fv + ((lane < NTAGS) ? trans[STOP_TAG * NTAGS + lane] : -1e30f);
    float best = -3.4e38f; int bi = 0;
    #pragma unroll
    for (int p = 0; p < NTAGS; p++) {
        float v = __shfl_sync(0xffffffffu, term, p);
        if (v > best) { best = v; bi = p; }
    }
    if (lane == 0) {
        if (out_size > 0) out[0] = best;
        int tag = bi;
        for (int t = TSEQ - 1; t >= 0; --t) {
            if (1 + t < out_size) out[1 + t] = (float)tag;
            tag = bp[t * NTAGS + tag];
        }
    }
}

// ---------------- launch -----------------------------------------------------
extern "C" void kernel_launch(void* const* d_in, const int* in_sizes, int n_in,
                              void* d_out, int out_size) {
    const float* features = (const float*)d_in[0];
    const float* conv1_w = (const float*)d_in[1];
    const float* conv1_b = (const float*)d_in[2];
    const float* conv3_w = (const float*)d_in[3];
    const float* conv3_b = (const float*)d_in[4];
    const float* conv5_w = (const float*)d_in[5];
    const float* conv5_b = (const float*)d_in[6];
    const float* wih0f = (const float*)d_in[7];
    const float* whh0f = (const float*)d_in[8];
    const float* bih0f = (const float*)d_in[9];
    const float* bhh0f = (const float*)d_in[10];
    const float* wih0r = (const float*)d_in[11];
    const float* whh0r = (const float*)d_in[12];
    const float* bih0r = (const float*)d_in[13];
    const float* bhh0r = (const float*)d_in[14];
    const float* wih1f = (const float*)d_in[15];
    const float* whh1f = (const float*)d_in[16];
    const float* bih1f = (const float*)d_in[17];
    const float* bhh1f = (const float*)d_in[18];
    const float* wih1r = (const float*)d_in[19];
    const float* whh1r = (const float*)d_in[20];
    const float* bih1r = (const float*)d_in[21];
    const float* bhh1r = (const float*)d_in[22];
    const float* h2t_w = (const float*)d_in[23];
    const float* h2t_b = (const float*)d_in[24];
    const float* trans = (const float*)d_in[25];
    float* out = (float*)d_out;

    float *p_x, *p_g0f, *p_g0r, *p_h0, *p_g1f, *p_g1r, *p_h1;
    unsigned long long *p_hp0, *p_hp1;
    cudaGetSymbolAddress((void**)&p_x, d_x);
    cudaGetSymbolAddress((void**)&p_g0f, d_g0f);
    cudaGetSymbolAddress((void**)&p_g0r, d_g0r);
    cudaGetSymbolAddress((void**)&p_h0, d_h0);
    cudaGetSymbolAddress((void**)&p_g1f, d_g1f);
    cudaGetSymbolAddress((void**)&p_g1r, d_g1r);
    cudaGetSymbolAddress((void**)&p_h1, d_h1);
    cudaGetSymbolAddress((void**)&p_hp0, d_hp0);
    cudaGetSymbolAddress((void**)&p_hp1, d_hp1);

    int nfill = (2 * TSEQ * 512) / 2;   // uint4 count per buffer
    fill_pairs_kernel<<<(nfill + 255) / 256, 256>>>();
    fill_out_kernel<<<(out_size + 255) / 256, 256>>>(out, out_size);

    conv_kernel<<<TSEQ, 256>>>(features, conv1_w, conv1_b, conv3_w, conv3_b, conv5_w, conv5_b);

    dim3 g0grid(GDIM / 128, TSEQ / 128, 2);
    gemm_bias_kernel<<<g0grid, 256>>>(p_x, DIN0,
                                      wih0f, wih0r, bih0f, bhh0f, bih0r, bhh0r,
                                      p_g0f, p_g0r);

    lstm_rec_kernel<<<128, 256>>>(p_g0f, p_g0r, whh0f, whh0r, p_h0, p_hp0);

    gemm_bias_kernel<<<g0grid, 256>>>(p_h0, 1024,
                                      wih1f, wih1r, bih1f, bhh1f, bih1r, bhh1r,
                                      p_g1f, p_g1r);

    lstm_rec_kernel<<<128, 256>>>(p_g1f, p_g1r, whh1f, whh1r, p_h1, p_hp1);

    h2t_kernel<<<TSEQ, 128>>>(p_h1, h2t_w, h2t_b);

    cudaFuncSetAttribute(viterbi_kernel, cudaFuncAttributeMaxDynamicSharedMemorySize,
                         TSEQ * NTAGS);
    viterbi_kernel<<<1, 32, TSEQ * NTAGS>>>(trans, out, out_size);
}

// round 7
// speedup vs baseline: 1.3711x; 1.3711x over previous
#include <cuda_runtime.h>
#include <cuda_bf16.h>
#include <math.h>

#define TSEQ 8192
#define HID 512
#define DIN0 1728
#define GDIM 2048   // 4*HID
#define NTAGS 27
#define START_TAG 25
#define STOP_TAG 26

// ---------------- static device scratch (no allocations allowed) -------------
__device__ float d_x[TSEQ * DIN0];          // conv features
__device__ float d_g0f[TSEQ * GDIM];        // layer0 fwd input-gates
__device__ float d_g0r[TSEQ * GDIM];        // layer0 bwd input-gates
__device__ float d_h0[TSEQ * 1024];         // layer0 output (fwd|bwd), plain
__device__ float d_g1f[TSEQ * GDIM];
__device__ float d_g1r[TSEQ * GDIM];
__device__ float d_h1[TSEQ * 1024];
__device__ float d_feats[TSEQ * NTAGS];
// tagged h pairs: [dir][t][512] of (tag<<32 | float_bits); one buffer per layer
__device__ unsigned long long d_hp0[2 * TSEQ * 512];
__device__ unsigned long long d_hp1[2 * TSEQ * 512];

// ---------------- packed f32x2 helpers (B300 FFMA2 — PTX-only path) ----------
__device__ __forceinline__ unsigned long long pack2(float lo, float hi) {
    unsigned long long r;
    asm("mov.b64 %0, {%1, %2};" : "=l"(r) : "f"(lo), "f"(hi));
    return r;
}
__device__ __forceinline__ void unpack2(unsigned long long v, float& lo, float& hi) {
    asm("mov.b64 {%0, %1}, %2;" : "=f"(lo), "=f"(hi) : "l"(v));
}
__device__ __forceinline__ unsigned long long fma2(unsigned long long a,
                                                   unsigned long long b,
                                                   unsigned long long c) {
    unsigned long long d;
    asm("fma.rn.f32x2 %0, %1, %2, %3;" : "=l"(d) : "l"(a), "l"(b), "l"(c));
    return d;
}

// ---------------- pair-buffer reset + output fill ----------------------------
__global__ void fill_pairs_kernel() {
    int i = blockIdx.x * blockDim.x + threadIdx.x;
    int n4 = (2 * TSEQ * 512) / 2;   // uint4 = 2 ull
    uint4 z = make_uint4(0u, 0u, 0u, 0u);
    if (i < n4) {
        ((uint4*)d_hp0)[i] = z;
        ((uint4*)d_hp1)[i] = z;
    }
}

__global__ void fill_out_kernel(float* out, int n) {
    int i = blockIdx.x * blockDim.x + threadIdx.x;
    if (i < n) out[i] = 0.0f;
}

// ---------------- conv front-end ---------------------------------------------
__global__ void conv_kernel(const float* __restrict__ features,
                            const float* __restrict__ w1, const float* __restrict__ b1,
                            const float* __restrict__ w3, const float* __restrict__ b3,
                            const float* __restrict__ w5, const float* __restrict__ b5) {
    __shared__ float f[448];
    int t = blockIdx.x, tid = threadIdx.x;
    for (int i = tid; i < 448; i += blockDim.x) f[i] = features[t * 448 + i];
    __syncthreads();
    for (int idx = tid; idx < DIN0; idx += blockDim.x) {
        float s;
        if (idx < 192) {
            int c = idx / 12, w = idx % 12;
            s = b1[c];
            #pragma unroll
            for (int kh = 0; kh < 7; kh++)
                #pragma unroll
                for (int kw = 0; kw < 4; kw++)
                    s = fmaf(f[kh * 64 + w * 4 + kw], w1[c * 28 + kh * 4 + kw], s);
        } else if (idx < 960) {
            int j = idx - 192;
            int c = j / 48, h = (j % 48) / 12, w = j % 12;
            s = b3[c];
            #pragma unroll
            for (int kh = 0; kh < 4; kh++)
                #pragma unroll
                for (int kw = 0; kw < 12; kw++)
                    s = fmaf(f[(h + kh) * 64 + w * 4 + kw], w3[c * 48 + kh * 12 + kw], s);
        } else {
            int j = idx - 960;
            int c = j / 48, h = (j % 48) / 12, w = j % 12;
            s = b5[c];
            #pragma unroll
            for (int kh = 0; kh < 4; kh++)
                #pragma unroll
                for (int kw = 0; kw < 20; kw++)
                    s = fmaf(f[(h + kh) * 64 + w * 4 + kw], w5[c * 80 + kh * 20 + kw], s);
        }
        d_x[t * DIN0 + idx] = s;
    }
}

// ---------------- GEMM: C = A[M,K] * B[N,K]^T + (bi + bh), N = 2048 ----------
// R4 structure (single buffer, two syncs) with FFMA2 packed inner product:
// acc[8][4] u64 = 8 m-rows x 4 n-col-pairs. fma.rn.f32x2 is IEEE fp32 per
// lane => bit-identical to the scalar version.
__global__ void __launch_bounds__(256)
gemm_bias_kernel(const float* __restrict__ A, int K,
                 const float* __restrict__ Bf, const float* __restrict__ Br,
                 const float* __restrict__ bif, const float* __restrict__ bhf,
                 const float* __restrict__ bir, const float* __restrict__ bhr,
                 float* __restrict__ Cf, float* __restrict__ Cr) {
    const float* B  = blockIdx.z ? Br  : Bf;
    const float* bi = blockIdx.z ? bir : bif;
    const float* bh = blockIdx.z ? bhr : bhf;
    float*       C  = blockIdx.z ? Cr  : Cf;

    __shared__ float As[16][132];
    __shared__ float Bs[16][132];

    int tid = threadIdx.x;
    int m0 = blockIdx.y * 128, n0 = blockIdx.x * 128;
    int tm = (tid >> 4) * 8;
    int tn = (tid & 15) * 8;

    unsigned long long acc[8][4];
    #pragma unroll
    for (int i = 0; i < 8; i++)
        #pragma unroll
        for (int j = 0; j < 4; j++) acc[i][j] = pack2(0.0f, 0.0f);

    int lr = tid >> 2;
    int lc = (tid & 3) * 4;
    const float* Ap = A + (size_t)(m0 + lr) * K + lc;
    const float* Bp = B + (size_t)(n0 + lr) * K + lc;

    for (int k0 = 0; k0 < K; k0 += 16) {
        float4 a0 = *(const float4*)(Ap + k0);
        float4 a1 = *(const float4*)(Ap + (size_t)64 * K + k0);
        float4 b0 = *(const float4*)(Bp + k0);
        float4 b1 = *(const float4*)(Bp + (size_t)64 * K + k0);
        __syncthreads();
        As[lc + 0][lr] = a0.x; As[lc + 1][lr] = a0.y; As[lc + 2][lr] = a0.z; As[lc + 3][lr] = a0.w;
        As[lc + 0][lr + 64] = a1.x; As[lc + 1][lr + 64] = a1.y; As[lc + 2][lr + 64] = a1.z; As[lc + 3][lr + 64] = a1.w;
        Bs[lc + 0][lr] = b0.x; Bs[lc + 1][lr] = b0.y; Bs[lc + 2][lr] = b0.z; Bs[lc + 3][lr] = b0.w;
        Bs[lc + 0][lr + 64] = b1.x; Bs[lc + 1][lr + 64] = b1.y; Bs[lc + 2][lr + 64] = b1.z; Bs[lc + 3][lr + 64] = b1.w;
        __syncthreads();
        #pragma unroll
        for (int kk = 0; kk < 16; kk++) {
            float4 av0 = *(const float4*)(&As[kk][tm]);
            float4 av1 = *(const float4*)(&As[kk][tm + 4]);
            float4 bv0 = *(const float4*)(&Bs[kk][tn]);
            float4 bv1 = *(const float4*)(&Bs[kk][tn + 4]);
            unsigned long long bb[4];
            bb[0] = pack2(bv0.x, bv0.y);
            bb[1] = pack2(bv0.z, bv0.w);
            bb[2] = pack2(bv1.x, bv1.y);
            bb[3] = pack2(bv1.z, bv1.w);
            float ar[8] = {av0.x, av0.y, av0.z, av0.w, av1.x, av1.y, av1.z, av1.w};
            #pragma unroll
            for (int i = 0; i < 8; i++) {
                unsigned long long aa = pack2(ar[i], ar[i]);
                #pragma unroll
                for (int j = 0; j < 4; j++)
                    acc[i][j] = fma2(aa, bb[j], acc[i][j]);
            }
        }
    }
    #pragma unroll
    for (int j = 0; j < 4; j++) {
        float bb0 = bi[n0 + tn + 2 * j]     + bh[n0 + tn + 2 * j];
        float bb1 = bi[n0 + tn + 2 * j + 1] + bh[n0 + tn + 2 * j + 1];
        #pragma unroll
        for (int i = 0; i < 8; i++) {
            float lo, hi;
            unpack2(acc[i][j], lo, hi);
            float* cp = C + (size_t)(m0 + tm + i) * GDIM + n0 + tn + 2 * j;
            cp[0] = lo + bb0;
            cp[1] = hi + bb1;
        }
    }
}

// ---------------- fast activations (saturating, __expf-based) ----------------
__device__ __forceinline__ float sigmoid_fast(float x) {
    return __fdividef(1.0f, 1.0f + __expf(-x));
}
__device__ __forceinline__ float tanh_fast(float x) {
    return 1.0f - __fdividef(2.0f, __expf(2.0f * x) + 1.0f);
}

// ---------------- persistent bidirectional LSTM recurrence -------------------
// R4 version (known good): tagged-word sync, serial activations on 8 lanes.
__global__ void __launch_bounds__(256, 1)
lstm_rec_kernel(const float* __restrict__ gxf, const float* __restrict__ gxr,
                const float* __restrict__ whhf, const float* __restrict__ whhr,
                float* __restrict__ hout, unsigned long long* hpairBase) {
    int b = blockIdx.x;
    int dir = b >> 6;                 // 0 fwd, 1 bwd
    int blk = b & 63;
    int cell0 = blk * 8;
    const float* gx  = dir ? gxr  : gxf;
    const float* whh = dir ? whhr : whhf;
    unsigned long long* hp = hpairBase + (size_t)dir * TSEQ * 512;

    int tid = threadIdx.x;
    int row = tid & 31;               // local gate row 0..31
    int seg = tid >> 5;               // 0..7 (64-wide h segment)
    int q = row >> 3, c = row & 7;
    int gr = q * HID + cell0 + c;     // global gate row in whh

    float4 w4[16];
    {
        const float4* wp = (const float4*)(whh + (size_t)gr * HID + seg * 64);
        #pragma unroll
        for (int i = 0; i < 16; i++) w4[i] = wp[i];
    }

    __shared__ float h_sm[512];
    __shared__ float partial[256];

    float cst = 0.0f;                 // cell state (valid on tid<8)

    // prefetch gx for step 0
    float gxv = 0.0f;
    if (tid < 32) {
        int t0 = dir ? (TSEQ - 1) : 0;
        gxv = __ldcg(gx + (size_t)t0 * GDIM + gr);
    }

    for (int s = 0; s < TSEQ; ++s) {
        int t = dir ? (TSEQ - 1 - s) : s;

        // prefetch gx for step s+1 (a full step of latency cover)
        float gx_next = 0.0f;
        if (tid < 32 && s + 1 < TSEQ) {
            int tn = dir ? (TSEQ - 2 - s) : (s + 1);
            gx_next = __ldcg(gx + (size_t)tn * GDIM + gr);
        }

        if (s > 0) {
            int tprev = dir ? (t + 1) : (t - 1);
            const unsigned long long* p0 = hp + (size_t)tprev * 512 + tid;
            const unsigned long long* p1 = p0 + 256;
            unsigned int want = (unsigned int)s;
            unsigned long long v0, v1;
            do {
                asm volatile("ld.relaxed.gpu.global.u64 %0, [%1];"
                             : "=l"(v0) : "l"(p0) : "memory");
                asm volatile("ld.relaxed.gpu.global.u64 %0, [%1];"
                             : "=l"(v1) : "l"(p1) : "memory");
            } while ((unsigned int)(v0 >> 32) != want ||
                     (unsigned int)(v1 >> 32) != want);
            h_sm[tid]       = __uint_as_float((unsigned int)v0);
            h_sm[tid + 256] = __uint_as_float((unsigned int)v1);
        } else {
            h_sm[tid] = 0.0f;
            h_sm[tid + 256] = 0.0f;
        }
        __syncthreads();

        // 64-wide partial dot, 4 independent accumulator chains (depth 16)
        float a0 = 0.f, a1 = 0.f, a2 = 0.f, a3 = 0.f;
        const float4* hv4 = (const float4*)(h_sm + seg * 64);
        #pragma unroll
        for (int i = 0; i < 16; i++) {
            float4 h = hv4[i];
            a0 = fmaf(w4[i].x, h.x, a0);
            a1 = fmaf(w4[i].y, h.y, a1);
            a2 = fmaf(w4[i].z, h.z, a2);
            a3 = fmaf(w4[i].w, h.w, a3);
        }
        partial[tid] = (a0 + a1) + (a2 + a3);
        __syncthreads();

        if (tid < 32) {
            float g = gxv;
            float s0 = partial[row]       + partial[32 + row];
            float s1 = partial[64 + row]  + partial[96 + row];
            float s2 = partial[128 + row] + partial[160 + row];
            float s3 = partial[192 + row] + partial[224 + row];
            g += (s0 + s1) + (s2 + s3);
            float gi = __shfl_sync(0xffffffffu, g, c);
            float gf = __shfl_sync(0xffffffffu, g, 8 + c);
            float gg = __shfl_sync(0xffffffffu, g, 16 + c);
            float go = __shfl_sync(0xffffffffu, g, 24 + c);
            if (tid < 8) {
                float fi = sigmoid_fast(gi);
                float ff = sigmoid_fast(gf);
                float fo = sigmoid_fast(go);
                cst = ff * cst + fi * tanh_fast(gg);
                float hv = fo * tanh_fast(cst);
                // plain copy for downstream kernels (kernel-order visibility)
                __stcg(hout + (size_t)t * 1024 + dir * HID + cell0 + c, hv);
                // tagged word: the sync carrier
                unsigned long long pv =
                    ((unsigned long long)(unsigned int)(s + 1) << 32) |
                    (unsigned long long)__float_as_uint(hv);
                unsigned long long* dst = hp + (size_t)t * 512 + cell0 + c;
                asm volatile("st.relaxed.gpu.global.u64 [%0], %1;"
                             :: "l"(dst), "l"(pv) : "memory");
            }
        }
        gxv = gx_next;
    }
}

// ---------------- hidden -> tag scores ---------------------------------------
__global__ void h2t_kernel(const float* __restrict__ h, const float* __restrict__ W,
                           const float* __restrict__ bt) {
    int t = blockIdx.x;
    int lane = threadIdx.x & 31, wrp = threadIdx.x >> 5;   // 4 warps
    for (int tag = wrp; tag < NTAGS; tag += 4) {
        float s = 0.0f;
        const float* hr = h + (size_t)t * 1024;
        const float* wr = W + (size_t)tag * 1024;
        for (int k = lane; k < 1024; k += 32) s = fmaf(hr[k], wr[k], s);
        #pragma unroll
        for (int o = 16; o; o >>= 1) s += __shfl_xor_sync(0xffffffffu, s, o);
        if (lane == 0) d_feats[t * NTAGS + tag] = s + bt[tag];
    }
}

// ---------------- Viterbi: 1 warp, SMEM fv broadcast, 4 contiguous chains ----
__global__ void viterbi_kernel(const float* __restrict__ trans,
                               float* __restrict__ out, int out_size) {
    extern __shared__ unsigned char bp[];   // [TSEQ][27] bytes (dynamic)
    __shared__ float fvs[28];
    int lane = threadIdx.x;

    float tr[28];
    #pragma unroll
    for (int p = 0; p < 28; p++)
        tr[p] = (lane < NTAGS && p < NTAGS) ? trans[lane * NTAGS + p] : -1e30f;

    float fv = (lane == START_TAG) ? 0.0f : -10000.0f;
    if (lane >= NTAGS) fv = -1e30f;
    if (lane == 0) fvs[27] = -1e30f;
    __syncwarp();

    for (int t = 0; t < TSEQ; t++) {
        float ft = (lane < NTAGS) ? __ldg(&d_feats[t * NTAGS + lane]) : 0.0f;
        if (lane < NTAGS) fvs[lane] = fv;
        __syncwarp();

        float m0 = -3.4e38f, m1 = -3.4e38f, m2 = -3.4e38f, m3 = -3.4e38f;
        int a0 = 0, a1 = 7, a2 = 14, a3 = 21;
        #pragma unroll
        for (int j = 0; j < 7; j++) {
            float s = fvs[j] + tr[j];
            if (s > m0) { m0 = s; a0 = j; }
        }
        #pragma unroll
        for (int j = 7; j < 14; j++) {
            float s = fvs[j] + tr[j];
            if (s > m1) { m1 = s; a1 = j; }
        }
        #pragma unroll
        for (int j = 14; j < 21; j++) {
            float s = fvs[j] + tr[j];
            if (s > m2) { m2 = s; a2 = j; }
        }
        #pragma unroll
        for (int j = 21; j < 28; j++) {
            float s = fvs[j] + tr[j];
            if (s > m3) { m3 = s; a3 = j; }
        }
        float m = m0; int a = a0;
        if (m1 > m) { m = m1; a = a1; }
        if (m2 > m) { m = m2; a = a2; }
        if (m3 > m) { m = m3; a = a3; }

        if (lane < NTAGS) bp[t * NTAGS + lane] = (unsigned char)a;
        fv = m + ft;
        __syncwarp();
    }

    float term = fv + ((lane < NTAGS) ? trans[STOP_TAG * NTAGS + lane] : -1e30f);
    float best = -3.4e38f; int bi = 0;
    #pragma unroll
    for (int p = 0; p < NTAGS; p++) {
        float v = __shfl_sync(0xffffffffu, term, p);
        if (v > best) { best = v; bi = p; }
    }
    if (lane == 0) {
        if (out_size > 0) out[0] = best;
        int tag = bi;
        for (int t = TSEQ - 1; t >= 0; --t) {
            if (1 + t < out_size) out[1 + t] = (float)tag;
            tag = bp[t * NTAGS + tag];
        }
    }
}

// ---------------- launch -----------------------------------------------------
extern "C" void kernel_launch(void* const* d_in, const int* in_sizes, int n_in,
                              void* d_out, int out_size) {
    const float* features = (const float*)d_in[0];
    const float* conv1_w = (const float*)d_in[1];
    const float* conv1_b = (const float*)d_in[2];
    const float* conv3_w = (const float*)d_in[3];
    const float* conv3_b = (const float*)d_in[4];
    const float* conv5_w = (const float*)d_in[5];
    const float* conv5_b = (const float*)d_in[6];
    const float* wih0f = (const float*)d_in[7];
    const float* whh0f = (const float*)d_in[8];
    const float* bih0f = (const float*)d_in[9];
    const float* bhh0f = (const float*)d_in[10];
    const float* wih0r = (const float*)d_in[11];
    const float* whh0r = (const float*)d_in[12];
    const float* bih0r = (const float*)d_in[13];
    const float* bhh0r = (const float*)d_in[14];
    const float* wih1f = (const float*)d_in[15];
    const float* whh1f = (const float*)d_in[16];
    const float* bih1f = (const float*)d_in[17];
    const float* bhh1f = (const float*)d_in[18];
    const float* wih1r = (const float*)d_in[19];
    const float* whh1r = (const float*)d_in[20];
    const float* bih1r = (const float*)d_in[21];
    const float* bhh1r = (const float*)d_in[22];
    const float* h2t_w = (const float*)d_in[23];
    const float* h2t_b = (const float*)d_in[24];
    const float* trans = (const float*)d_in[25];
    float* out = (float*)d_out;

    float *p_x, *p_g0f, *p_g0r, *p_h0, *p_g1f, *p_g1r, *p_h1;
    unsigned long long *p_hp0, *p_hp1;
    cudaGetSymbolAddress((void**)&p_x, d_x);
    cudaGetSymbolAddress((void**)&p_g0f, d_g0f);
    cudaGetSymbolAddress((void**)&p_g0r, d_g0r);
    cudaGetSymbolAddress((void**)&p_h0, d_h0);
    cudaGetSymbolAddress((void**)&p_g1f, d_g1f);
    cudaGetSymbolAddress((void**)&p_g1r, d_g1r);
    cudaGetSymbolAddress((void**)&p_h1, d_h1);
    cudaGetSymbolAddress((void**)&p_hp0, d_hp0);
    cudaGetSymbolAddress((void**)&p_hp1, d_hp1);

    int nfill = (2 * TSEQ * 512) / 2;   // uint4 count per buffer
    fill_pairs_kernel<<<(nfill + 255) / 256, 256>>>();
    fill_out_kernel<<<(out_size + 255) / 256, 256>>>(out, out_size);

    conv_kernel<<<TSEQ, 256>>>(features, conv1_w, conv1_b, conv3_w, conv3_b, conv5_w, conv5_b);

    dim3 g0grid(GDIM / 128, TSEQ / 128, 2);
    gemm_bias_kernel<<<g0grid, 256>>>(p_x, DIN0,
                                      wih0f, wih0r, bih0f, bhh0f, bih0r, bhh0r,
                                      p_g0f, p_g0r);

    lstm_rec_kernel<<<128, 256>>>(p_g0f, p_g0r, whh0f, whh0r, p_h0, p_hp0);

    gemm_bias_kernel<<<g0grid, 256>>>(p_h0, 1024,
                                      wih1f, wih1r, bih1f, bhh1f, bih1r, bhh1r,
                                      p_g1f, p_g1r);

    lstm_rec_kernel<<<128, 256>>>(p_g1f, p_g1r, whh1f, whh1r, p_h1, p_hp1);

    h2t_kernel<<<TSEQ, 128>>>(p_h1, h2t_w, h2t_b);

    cudaFuncSetAttribute(viterbi_kernel, cudaFuncAttributeMaxDynamicSharedMemorySize,
                         TSEQ * NTAGS);
    viterbi_kernel<<<1, 32, TSEQ * NTAGS>>>(trans, out, out_size);
}